// round 17
// baseline (speedup 1.0000x reference)
#include <cuda_runtime.h>
#include <cuda_bf16.h>
#include <math.h>
#include <stdint.h>

#define G_   64
#define T_   10
#define H_   256
#define H4_  1024

// Output offsets (tuple flattened: gamma, beta, delta, hN, cN)
#define OFF_GAMMA 0
#define OFF_BETA  640
#define OFF_DELTA 164480
#define OFF_HN    328320
#define OFF_CN    361088

// Scratch
__device__ float g_h2  [G_ * T_ * H_];
__device__ float g_lin1[G_ * T_ * H_];
__device__ int   g_dummy;

__device__ __forceinline__ float fast_tanh(float x) {
    float r; asm("tanh.approx.f32 %0, %1;" : "=f"(r) : "f"(x)); return r;
}
__device__ __forceinline__ float sigf(float x) {
    return fmaf(fast_tanh(0.5f * x), 0.5f, 0.5f);
}
__device__ __forceinline__ void fma2(unsigned long long& acc, unsigned long long a, unsigned long long b) {
    asm("fma.rn.f32x2 %0, %1, %2, %0;" : "+l"(acc) : "l"(a), "l"(b));
}
__device__ __forceinline__ float unpack_sum(unsigned long long v) {
    unsigned int lo, hi;
    asm("mov.b64 {%0, %1}, %2;" : "=r"(lo), "=r"(hi) : "l"(v));
    return __uint_as_float(lo) + __uint_as_float(hi);
}
__device__ __forceinline__ unsigned int smem_u32(const void* p) {
    unsigned int a;
    asm("{ .reg .u64 t; cvta.to.shared.u64 t, %1; cvt.u32.u64 %0, t; }" : "=r"(a) : "l"(p));
    return a;
}
__device__ __forceinline__ void st_async_f32(unsigned int saddr, unsigned int smbar,
                                             unsigned int rank, float v) {
    asm volatile(
        "{ .reg .b32 ra, rb;\n"
        "  mapa.shared::cluster.u32 ra, %0, %2;\n"
        "  mapa.shared::cluster.u32 rb, %1, %2;\n"
        "  st.async.shared::cluster.mbarrier::complete_tx::bytes.b32 [ra], %3, [rb]; }"
        :: "r"(saddr), "r"(smbar), "r"(rank), "f"(v) : "memory");
}
__device__ __forceinline__ void mbar_wait_cl(unsigned int addr, unsigned int parity) {
    unsigned int done;
    do {
        asm volatile(
            "{ .reg .pred p; mbarrier.try_wait.parity.acquire.cluster.shared::cta.b64 p, [%1], %2, 0x989680; selp.b32 %0,1,0,p; }"
            : "=r"(done) : "r"(addr), "r"(parity) : "memory");
    } while (!done);
}
#define CLUSTER_SYNC() do { \
    asm volatile("barrier.cluster.arrive.aligned;" ::: "memory"); \
    asm volatile("barrier.cluster.wait.aligned;"   ::: "memory"); } while (0)

__device__ __forceinline__ void bulk_g2s(unsigned int dst, const void* src,
                                         unsigned int bytes, unsigned int mbar) {
    asm volatile(
        "cp.async.bulk.shared::cluster.global.mbarrier::complete_tx::bytes [%0], [%1], %2, [%3];"
        :: "r"(dst), "l"(src), "r"(bytes), "r"(mbar) : "memory");
}
__device__ __forceinline__ void mbar_init(unsigned int addr, unsigned int cnt) {
    asm volatile("mbarrier.init.shared.b64 [%0], %1;" :: "r"(addr), "r"(cnt) : "memory");
}
__device__ __forceinline__ void mbar_expect(unsigned int addr, unsigned int bytes) {
    asm volatile("mbarrier.arrive.expect_tx.shared.b64 _, [%0], %1;" :: "r"(addr), "r"(bytes) : "memory");
}
__device__ __forceinline__ void mbar_wait(unsigned int addr, unsigned int parity) {
    unsigned int done;
    do {
        asm volatile(
            "{ .reg .pred p; mbarrier.try_wait.parity.acquire.cta.shared::cta.b64 p, [%1], %2, 0x989680; selp.b32 %0,1,0,p; }"
            : "=r"(done) : "r"(addr), "r"(parity) : "memory");
    } while (!done);
}

// Dummy kernel: aligns the ncu capture slot (4th launch is captured).
__global__ void dummy_kernel(int tag) {
    if (tag == 12345 && threadIdx.x == 0) g_dummy = tag;
}

// ---------------------------------------------------------------------------
// Fused 2-layer LSTM, one group per 8-CTA cluster, wave-staggered.
// ROUND-9 VERSION VERBATIM (best measured: 212us).
// ---------------------------------------------------------------------------
#define SMEM_BYTES 215040

__global__ void __cluster_dims__(8, 1, 1) __launch_bounds__(512, 1)
lstm_fused2_kernel(const float* __restrict__ Wih0, const float* __restrict__ Whh0,
                   const float* __restrict__ bih0, const float* __restrict__ bhh0,
                   const float* __restrict__ Wih1, const float* __restrict__ Whh1,
                   const float* __restrict__ bih1, const float* __restrict__ bhh1,
                   const float* __restrict__ data, float* __restrict__ out)
{
    extern __shared__ __align__(16) char smem[];
    float* A      = (float*)(smem);
    float* B      = (float*)(smem + 65536);
    float* C      = (float*)(smem + 131072);
    float* xs     = (float*)(smem + 196608);
    float* xgp    = (float*)(smem + 206848);
    float* h_buf  = (float*)(smem + 211968);
    const unsigned int mb  = smem_u32(smem + 214528);
    const unsigned int mbF = smem_u32(smem + 214592);

    const int g    = blockIdx.x >> 3;
    const int crk  = blockIdx.x & 7;
    const int tid  = threadIdx.x;

    const int rl   = tid >> 2;
    const int q    = tid & 3;
    const int gate = rl >> 5;
    const int ul   = rl & 31;
    const int grow = gate * 256 + crk * 32 + ul;
    const int qh   = q ^ (q << 1);

    const int l    = tid & 31;
    const int w    = tid >> 5;
    const int unit = w * 2 + ((l >> 4) & 1);
    const int g2   = (l >> 2) & 3;
    const int q2   = l & 3;
    const int rl2  = g2 * 32 + unit;
    const int qh2  = q2 ^ (q2 << 1);
    const int base = (l & 16) | q2;
    const int k    = l & 15;

    if (tid == 0) {
        #pragma unroll
        for (int i = 0; i < 8; i++) mbar_init(mb + i * 8, 1);
        mbar_init(mbF + 0, 1); mbar_init(mbF + 8, 1);
        mbar_expect(mbF + 0, 1024);
        mbar_expect(mbF + 8, 1024);
    }
    __syncthreads();

    auto issue2 = [&](unsigned int mbar, float* buf, const float* M, int b0, int b1) {
        mbar_expect(mbar, 65536);
        bulk_g2s(smem_u32(buf),         M + ((size_t)g * 1024 + b0 * 256 + crk * 32) * 256, 32768, mbar);
        bulk_g2s(smem_u32(buf) + 32768, M + ((size_t)g * 1024 + b1 * 256 + crk * 32) * 256, 32768, mbar);
    };

    if (tid == 0) {
        issue2(mb + 0,  A, Wih0, 0, 1);
        issue2(mb + 8,  B, Wih0, 2, 3);
        issue2(mb + 16, C, Whh0, 0, 1);
    }

    for (int e = tid; e < T_ * 256; e += 512) {
        int t = e >> 8, u = e & 255;
        xs[t * 256 + (u ^ ((u & 0xC0) >> 3))] = data[((size_t)t * G_ + g) * 256 + u];
    }
    if (tid < 256) h_buf[tid] = 0.0f;
    __syncthreads();

    ulonglong2 wreg[16];

    auto run_xg = [&](const float* lobuf, const float* hibuf,
                      const float* bihp, const float* bhhp) {
        const ulonglong2* wsrc = (const ulonglong2*)((rl < 64) ? (lobuf + rl * 256)
                                                               : (hibuf + (rl - 64) * 256));
        const ulonglong2* xs2 = (const ulonglong2*)xs;
        unsigned long long xa[T_];
        #pragma unroll
        for (int t = 0; t < T_; t++) xa[t] = 0ull;
        #pragma unroll 2
        for (int i = 0; i < 16; i++) {
            ulonglong2 wv = wsrc[16 * q + (i ^ q)];
            const int xi = 16 * q + (i ^ qh);
            #pragma unroll
            for (int t = 0; t < T_; t++) {
                ulonglong2 x = xs2[t * 64 + xi];
                fma2(xa[t], wv.x, x.x);
                fma2(xa[t], wv.y, x.y);
            }
        }
        const float bias = (q == 0)
            ? bihp[(size_t)g * H4_ + grow] + bhhp[(size_t)g * H4_ + grow] : 0.0f;
        #pragma unroll
        for (int t = 0; t < T_; t++) {
            float s = unpack_sum(xa[t]);
            s += __shfl_xor_sync(0xffffffffu, s, 1);
            s += __shfl_xor_sync(0xffffffffu, s, 2);
            if (q == 0) xgp[t * 128 + rl] = s + bias;
        }
        __syncthreads();
    };

    auto load_wreg = [&](const float* lobuf, const float* hibuf) {
        const ulonglong2* src = (const ulonglong2*)((rl2 < 64) ? (lobuf + rl2 * 256)
                                                               : (hibuf + (rl2 - 64) * 256));
        #pragma unroll
        for (int i = 0; i < 16; i++) wreg[i] = src[16 * q2 + (i ^ q2)];
        __syncthreads();
    };

    const unsigned int hbase = smem_u32(h_buf);
    unsigned int f0 = 0, f1 = 0;

    auto run_rec = [&](int layer) {
        float* hdst = g_h2 + (size_t)g * T_ * 256;
        float c_reg = 0.0f, h_last = 0.0f;
        for (int t = 0; t < T_; t++) {
            const int br = t & 1;
            if (t > 0) {
                if (br) { mbar_wait_cl(mbF + 8, f1); f1 ^= 1; if (tid == 0) mbar_expect(mbF + 8, 1024); }
                else    { mbar_wait_cl(mbF + 0, f0); f0 ^= 1; if (tid == 0) mbar_expect(mbF + 0, 1024); }
            }
            if (layer == 0 && t > 0 && l < 16)
                xs[(t - 1) * 256 + w * 16 + l] = h_buf[br * 256 + w * 16 + l];

            const ulonglong2* h2 = (const ulonglong2*)(h_buf + br * 256);
            unsigned long long a0 = 0ull, a1 = 0ull;
            #pragma unroll
            for (int i = 0; i < 16; i++) {
                ulonglong2 h = h2[16 * q2 + (i ^ qh2)];
                fma2(a0, wreg[i].x, h.x);
                fma2(a1, wreg[i].y, h.y);
            }
            float s = unpack_sum(a0) + unpack_sum(a1);
            s += __shfl_xor_sync(0xffffffffu, s, 1);
            s += __shfl_xor_sync(0xffffffffu, s, 2);
            s += xgp[t * 128 + rl2];

            float ig = __shfl_sync(0xffffffffu, s, base + 0);
            float fg = __shfl_sync(0xffffffffu, s, base + 4);
            float gg = __shfl_sync(0xffffffffu, s, base + 8);
            float og = __shfl_sync(0xffffffffu, s, base + 12);

            if (k < 8) {
                c_reg = sigf(fg) * c_reg + sigf(ig) * fast_tanh(gg);
                float h = sigf(og) * fast_tanh(c_reg);
                h_last = h;
                if (layer && k == 0) hdst[(size_t)t * 256 + crk * 32 + unit] = h;
                const int bw = br ^ 1;
                const int gu = crk * 32 + unit;
                const int phys = gu ^ ((gu & 0xC0) >> 3);
                st_async_f32(hbase + (unsigned)(bw * 256 + phys) * 4u,
                             mbF + (unsigned)bw * 8u, (unsigned)k, h);
            }
        }
        mbar_wait_cl(mbF + 0, f0); f0 ^= 1; if (tid == 0) mbar_expect(mbF + 0, 1024);
        if (layer == 0 && l < 16)
            xs[(T_ - 1) * 256 + w * 16 + l] = h_buf[w * 16 + l];
        __syncthreads();

        if (k == 0) {
            out[OFF_HN + (size_t)g * 512 + layer * 256 + crk * 32 + unit] = h_last;
            out[OFF_CN + (size_t)g * 512 + layer * 256 + crk * 32 + unit] = c_reg;
        }
    };

    mbar_wait(rl < 64 ? mb + 0 : mb + 8, 0);
    run_xg(A, B, bih0, bhh0);
    if (tid == 0) issue2(mb + 24, B, Whh0, 2, 3);
    {
        mbar_wait(rl2 < 64 ? mb + 16 : mb + 24, 0);
        load_wreg(C, B);
    }
    if (tid == 0) {
        issue2(mb + 32, A, Wih1, 0, 1);
        issue2(mb + 40, C, Wih1, 2, 3);
        issue2(mb + 48, B, Whh1, 0, 1);
    }
    CLUSTER_SYNC();
    run_rec(0);

    if (tid < 256) h_buf[tid] = 0.0f;
    __syncthreads();
    mbar_wait(rl < 64 ? mb + 32 : mb + 40, 0);
    run_xg(A, C, bih1, bhh1);
    if (tid == 0) issue2(mb + 56, A, Whh1, 2, 3);
    {
        mbar_wait(rl2 < 64 ? mb + 48 : mb + 56, 0);
        load_wreg(B, A);
    }
    CLUSTER_SYNC();
    run_rec(1);

    CLUSTER_SYNC();
}

// ---------------------------------------------------------------------------
// Tail v2: TMA-staged weights, conflict-floor SMEM compute.
// Grid: 64 blocks (one per group) x 512 threads.
// Warp map: r4 = lane>>3 (4 rows), c8 = lane&7 (8 lanes per row, each owns
// 8 float4 of the row, read in rotated order (i+c8+2*r4)&7 -> LDS at 4-phase
// floor). Warp w covers chunk rows (w&7)*4..+4 for t-half (w>>3)*5..+5.
// Stage1: Wlin chunks (mb 0..7). Stage2: W1 (mb 8..15) + W2 (mb 16..23).
// ---------------------------------------------------------------------------
#define TAIL_SMEM 162048

__global__ void __launch_bounds__(512)
tail_kernel(const float* __restrict__ Wlin, const float* __restrict__ blin,
            const float* __restrict__ W1, const float* __restrict__ b1,
            const float* __restrict__ W2, const float* __restrict__ b2,
            const float* __restrict__ Wd, const float* __restrict__ bd,
            float* __restrict__ out)
{
    extern __shared__ __align__(16) char tsm[];
    float* hs  = (float*)(tsm);            // 10KB  [t*256+j]
    float* fcs = (float*)(tsm + 10240);    // 10KB
    float* l1s = (float*)(tsm + 20480);    // 10KB
    float* bW[2] = { (float*)(tsm + 30720), (float*)(tsm + 63488)  };  // Wlin/W1 chunks
    float* bV[2] = { (float*)(tsm + 96256), (float*)(tsm + 129024) };  // W2 chunks
    const unsigned int mbT = smem_u32(tsm + 161792);   // 24 single-use mbars
#define TMB(i) (mbT + (unsigned)(i) * 8u)

    const int g    = blockIdx.x;
    const int tid  = threadIdx.x;
    const int lane = tid & 31;
    const int w    = tid >> 5;
    const int r4   = lane >> 3;            // row within warp's 4
    const int c8   = lane & 7;             // column-eighth
    const int rr   = (w & 7) * 4 + r4;     // row within 32-row chunk
    const int th   = w >> 3;               // t-half
    const int rot  = (c8 + 2 * r4) & 7;    // LDS rotation

    if (tid == 0) {
        #pragma unroll
        for (int i = 0; i < 24; i++) mbar_init(TMB(i), 1);
    }
    __syncthreads();

    auto issue_chunk = [&](unsigned int m, float* buf, const float* M, int c) {
        mbar_expect(m, 32768);
        bulk_g2s(smem_u32(buf), M + (size_t)c * 8192, 32768, m);
    };

    if (tid == 0) {
        issue_chunk(TMB(0),  bW[0], Wlin + (size_t)g * 65536, 0);
        issue_chunk(TMB(1),  bW[1], Wlin + (size_t)g * 65536, 1);
        issue_chunk(TMB(16), bV[0], W2, 0);     // prefetch W2 for stage 2
        issue_chunk(TMB(17), bV[1], W2, 1);
    }

    // hs load (coalesced)
    {
        const float4* hp4 = (const float4*)(g_h2 + (size_t)g * T_ * 256);
        float4* hw = (float4*)hs;
        for (int e = tid; e < 640; e += 512) hw[e] = hp4[e];
    }
    __syncthreads();

    // ---------------- stage 1: fc = hs @ Wlin^T + blin ----------------
    for (int c = 0; c < 8; c++) {
        mbar_wait(TMB(c), 0);
        const float4* Wb = (const float4*)bW[c & 1];
        const float4* X4 = (const float4*)hs;
        const int row = c * 32 + rr;

        float4 wr[8];
        #pragma unroll
        for (int i = 0; i < 8; i++) {
            const int m = (i + rot) & 7;
            wr[m] = Wb[rr * 64 + c8 * 8 + m];
        }
        const float bias = blin[(size_t)g * 256 + row];
        #pragma unroll
        for (int tt = 0; tt < 5; tt++) {
            const int t = th * 5 + tt;
            float acc = 0.0f;
            #pragma unroll
            for (int i = 0; i < 8; i++) {
                const int m = (i + rot) & 7;
                float4 x = X4[t * 64 + c8 * 8 + m];
                acc += wr[m].x * x.x + wr[m].y * x.y + wr[m].z * x.z + wr[m].w * x.w;
            }
            acc += __shfl_xor_sync(0xffffffffu, acc, 1);
            acc += __shfl_xor_sync(0xffffffffu, acc, 2);
            acc += __shfl_xor_sync(0xffffffffu, acc, 4);
            if (c8 == 0) fcs[t * 256 + row] = acc + bias;
        }
        __syncthreads();   // chunk reads done; fcs rows written
        if (tid == 0) {
            if (c + 2 < 8) issue_chunk(TMB(c + 2), bW[c & 1], Wlin + (size_t)g * 65536, c + 2);
            else           issue_chunk(TMB(8 + (c - 6)), bW[c & 1], W1, c - 6);  // W1 c0,c1
        }
    }

    // ---------------- stage 2: lin1 = fc@W1^T + b1 ; beta = softplus(fc@W2^T + b2) ----
    for (int c = 0; c < 8; c++) {
        mbar_wait(TMB(8 + c), 0);
        mbar_wait(TMB(16 + c), 0);
        const float4* Wb1 = (const float4*)bW[c & 1];
        const float4* Wb2 = (const float4*)bV[c & 1];
        const float4* X4  = (const float4*)fcs;
        const int row = c * 32 + rr;

        float4 u[8], v[8];
        #pragma unroll
        for (int i = 0; i < 8; i++) {
            const int m = (i + rot) & 7;
            u[m] = Wb1[rr * 64 + c8 * 8 + m];
            v[m] = Wb2[rr * 64 + c8 * 8 + m];
        }
        const float bias1 = b1[row];
        const float bias2 = b2[row];
        #pragma unroll
        for (int tt = 0; tt < 5; tt++) {
            const int t = th * 5 + tt;
            float a1 = 0.0f, a2 = 0.0f;
            #pragma unroll
            for (int i = 0; i < 8; i++) {
                const int m = (i + rot) & 7;
                float4 x = X4[t * 64 + c8 * 8 + m];
                a1 += u[m].x * x.x + u[m].y * x.y + u[m].z * x.z + u[m].w * x.w;
                a2 += v[m].x * x.x + v[m].y * x.y + v[m].z * x.z + v[m].w * x.w;
            }
            a1 += __shfl_xor_sync(0xffffffffu, a1, 1);
            a1 += __shfl_xor_sync(0xffffffffu, a1, 2);
            a1 += __shfl_xor_sync(0xffffffffu, a1, 4);
            a2 += __shfl_xor_sync(0xffffffffu, a2, 1);
            a2 += __shfl_xor_sync(0xffffffffu, a2, 2);
            a2 += __shfl_xor_sync(0xffffffffu, a2, 4);
            if (c8 == 0) {
                const size_t idx = ((size_t)g * T_ + t) * 256 + row;
                const float lv = a1 + bias1;
                l1s[t * 256 + row] = lv;
                g_lin1[idx] = lv;
                const float x = a2 + bias2;
                out[OFF_BETA + idx] = (x > 20.0f) ? x : log1pf(__expf(x));
            }
        }
        __syncthreads();
        if (tid == 0 && c + 2 < 8) {
            issue_chunk(TMB(8 + c + 2),  bW[c & 1], W1, c + 2);
            issue_chunk(TMB(16 + c + 2), bV[c & 1], W2, c + 2);
        }
    }

    // ---------------- stage 3: gamma (warp per t) ----------------
    if (w < T_) {
        const float4* lr  = (const float4*)(l1s + w * 256);
        const float4* wd4 = (const float4*)Wd;
        float4 l0 = lr[lane],      d0 = wd4[lane];
        float4 l1 = lr[lane + 32], d1 = wd4[lane + 32];
        float s = l0.x * d0.x + l0.y * d0.y + l0.z * d0.z + l0.w * d0.w
                + l1.x * d1.x + l1.y * d1.y + l1.z * d1.z + l1.w * d1.w;
        #pragma unroll
        for (int o = 16; o > 0; o >>= 1) s += __shfl_xor_sync(0xffffffffu, s, o);
        if (lane == 0) out[OFF_GAMMA + (size_t)g * T_ + w] = s + bd[0];
    }
}

// ---------------------------------------------------------------------------
// Softmax over groups. Grid: (10, 4) x 64 threads.
// ---------------------------------------------------------------------------
__global__ void softmax_kernel(float* __restrict__ out)
{
    const int t = blockIdx.x;
    const int j = blockIdx.y * 64 + threadIdx.x;
    float v[G_];
    float m = -1e30f;
    #pragma unroll
    for (int g = 0; g < G_; g++) {
        v[g] = g_lin1[((size_t)g * T_ + t) * 256 + j];
        m = fmaxf(m, v[g]);
    }
    float s = 0.0f;
    #pragma unroll
    for (int g = 0; g < G_; g++) { v[g] = __expf(v[g] - m); s += v[g]; }
    const float inv = __fdividef(1.0f, s);
    #pragma unroll
    for (int g = 0; g < G_; g++)
        out[OFF_DELTA + ((size_t)g * T_ + t) * 256 + j] = v[g] * inv;
}

// ---------------------------------------------------------------------------
extern "C" void kernel_launch(void* const* d_in, const int* in_sizes, int n_in,
                              void* d_out, int out_size)
{
    const float* data = (const float*)d_in[0];
    const float* Wih0 = (const float*)d_in[1];
    const float* Whh0 = (const float*)d_in[2];
    const float* bih0 = (const float*)d_in[3];
    const float* bhh0 = (const float*)d_in[4];
    const float* Wih1 = (const float*)d_in[5];
    const float* Whh1 = (const float*)d_in[6];
    const float* bih1 = (const float*)d_in[7];
    const float* bhh1 = (const float*)d_in[8];
    const float* Wlin = (const float*)d_in[9];
    const float* blin = (const float*)d_in[10];
    const float* W1   = (const float*)d_in[11];
    const float* b1   = (const float*)d_in[12];
    const float* W2   = (const float*)d_in[13];
    const float* b2   = (const float*)d_in[14];
    const float* Wd   = (const float*)d_in[15];
    const float* bd   = (const float*)d_in[16];
    float* out = (float*)d_out;

    cudaFuncSetAttribute(lstm_fused2_kernel,
                         cudaFuncAttributeMaxDynamicSharedMemorySize, SMEM_BYTES);
    cudaFuncSetAttribute(tail_kernel,
                         cudaFuncAttributeMaxDynamicSharedMemorySize, TAIL_SMEM);

    // 2 dummies: the 4th launch (captured by ncu) is the NEW tail_kernel.
    dummy_kernel<<<1, 32>>>(0);
    dummy_kernel<<<1, 32>>>(1);

    lstm_fused2_kernel<<<G_ * 8, 512, SMEM_BYTES>>>(Wih0, Whh0, bih0, bhh0,
                                                    Wih1, Whh1, bih1, bhh1, data, out);
    tail_kernel<<<64, 512, TAIL_SMEM>>>(Wlin, blin, W1, b1, W2, b2, Wd, bd, out);
    softmax_kernel<<<dim3(10, 4), 64>>>(out);
}